// round 15
// baseline (speedup 1.0000x reference)
#include <cuda_runtime.h>
#include <cuda_bf16.h>
#include <cstdint>

#define TPB   256
#define WARPS 8

// ---- smem layout (bytes) ----
// A:  per-warp h1 tile (rn bf16), 32 rows x 128 cols, 256B rows, swizzled.
// B:  rn(W2^T) 128x128 bf16, swizzled.
// ZW: per-warp z0/wd tables (layer 1 is z = z0 + t*wd; sphere tracing is
//     linear in p).  T: per-warp accumulated march distance.
// B fragments for n2 in {0,1} are hoisted into registers before the march
// loop (64 regs): B is step-invariant, so 16 of 80 ldsm.x4/step disappear.
static constexpr int A_OFF   = 0;         // 8 * 8192   = 65536
static constexpr int BH_OFF  = 65536;     //              32768
static constexpr int ZW_OFF  = 98304;     // 8 * 16384  = 131072
static constexpr int BW_OFF  = 229376;    // 128 float2 = 1024
static constexpr int T_OFF   = 230400;    // 8 * 32 f32 = 1024
static constexpr int SMEM_TOTAL = 231424; // < 232448 (227KB cap)

static __device__ __forceinline__ uint32_t smem_u32(const void* p) {
    uint32_t a;
    asm("{ .reg .u64 t; cvta.to.shared.u64 t, %1; cvt.u32.u64 %0, t; }"
        : "=r"(a) : "l"(p));
    return a;
}

static __device__ __forceinline__ void ldsm_x4(uint32_t (&r)[4], uint32_t addr) {
    asm volatile("ldmatrix.sync.aligned.m8n8.x4.shared.b16 {%0,%1,%2,%3}, [%4];"
                 : "=r"(r[0]), "=r"(r[1]), "=r"(r[2]), "=r"(r[3]) : "r"(addr));
}

static __device__ __forceinline__ void mma_bf16(float* d, const uint32_t (&a)[4],
                                                uint32_t b0, uint32_t b1) {
    asm volatile(
        "mma.sync.aligned.m16n8k16.row.col.f32.bf16.bf16.f32 "
        "{%0,%1,%2,%3}, {%4,%5,%6,%7}, {%8,%9}, {%0,%1,%2,%3};"
        : "+f"(d[0]), "+f"(d[1]), "+f"(d[2]), "+f"(d[3])
        : "r"(a[0]), "r"(a[1]), "r"(a[2]), "r"(a[3]), "r"(b0), "r"(b1));
}

// bf16x2 pack of (lo, hi) with rn.
static __device__ __forceinline__ uint32_t bf16x2_rn(float lo, float hi) {
    uint32_t r;
    asm("cvt.rn.bf16x2.f32 %0, %1, %2;" : "=r"(r) : "f"(hi), "f"(lo));
    return r;
}

// Packed bf16x2 fma / relu.
static __device__ __forceinline__ uint32_t hfma2(uint32_t a, uint32_t b, uint32_t c) {
    uint32_t r;
    asm("fma.rn.bf16x2 %0, %1, %2, %3;" : "=r"(r) : "r"(a), "r"(b), "r"(c));
    return r;
}
static __device__ __forceinline__ uint32_t relu2(uint32_t a) {
    uint32_t r;
    asm("max.bf16x2 %0, %1, %2;" : "=r"(r) : "r"(a), "r"(0u));
    return r;
}

extern __shared__ char smem[];

__global__ void __launch_bounds__(TPB)
sdf_march_mma(const float* __restrict__ pos, const float* __restrict__ dir,
              const float* __restrict__ W1, const float* __restrict__ b1,
              const float* __restrict__ W2, const float* __restrict__ b2,
              const float* __restrict__ W3, const float* __restrict__ b3,
              const int* __restrict__ steps_ptr, float* __restrict__ out)
{
    const int tid  = threadIdx.x;
    const int wid  = tid >> 5;
    const int lane = tid & 31;
    const uint32_t sbase = smem_u32(smem);

    // ---- Stage B = rn(W2^T), swizzled ----
    for (int idx = tid; idx < 128 * 128; idx += TPB) {
        const int k = idx >> 7;    // reduction dim i
        const int n = idx & 127;   // output dim j
        const uint32_t off = (uint32_t)n * 256u
                           + (uint32_t)(((k >> 3) ^ (n & 7)) << 4)
                           + (uint32_t)((k & 7) << 1);
        *(__nv_bfloat16*)(smem + BH_OFF + off) = __float2bfloat16(W2[idx]);
    }
    if (tid < 128) {
        ((float2*)(smem + BW_OFF))[tid] = make_float2(b2[tid], W3[tid]);
    }

    // ---- Stage ZW: z0 = W1^T p0 + b1, wd = W1^T d for this warp's rays ----
    {
        const int i0 = lane * 4;
        float w1x[4], w1y[4], w1z[4], b1c[4];
        #pragma unroll
        for (int c = 0; c < 4; ++c) {
            w1x[c] = W1[i0 + c];
            w1y[c] = W1[128 + i0 + c];
            w1z[c] = W1[256 + i0 + c];
            b1c[c] = b1[i0 + c];
        }
        char* zw_warp = smem + ZW_OFF + wid * 16384;
        for (int r = 0; r < 32; ++r) {
            const int gr = blockIdx.x * TPB + wid * 32 + r;
            const float px = pos[gr * 3 + 0], py = pos[gr * 3 + 1], pz = pos[gr * 3 + 2];
            const float qx = dir[gr * 3 + 0], qy = dir[gr * 3 + 1], qz = dir[gr * 3 + 2];
            float z0[4], wd[4];
            #pragma unroll
            for (int c = 0; c < 4; ++c) {
                z0[c] = fmaf(px, w1x[c], fmaf(py, w1y[c], fmaf(pz, w1z[c], b1c[c])));
                wd[c] = fmaf(qx, w1x[c], fmaf(qy, w1y[c], qz * w1z[c]));
            }
            uint4 pk;
            pk.x = bf16x2_rn(z0[0], z0[1]);
            pk.y = bf16x2_rn(wd[0], wd[1]);
            pk.z = bf16x2_rn(z0[2], z0[3]);
            pk.w = bf16x2_rn(wd[2], wd[3]);
            *(uint4*)(zw_warp + r * 512 + lane * 16) = pk;
        }
    }

    // ---- Per-ray state: t = 0 ----
    const int ray = blockIdx.x * TPB + tid;
    const float dx = dir[ray * 3 + 0], dy = dir[ray * 3 + 1], dz = dir[ray * 3 + 2];
    float* t_tab = (float*)(smem + T_OFF) + wid * 32;
    t_tab[lane] = 0.f;

    const float bias3 = b3[0];
    const int nsteps = steps_ptr[0];

    __syncthreads();  // B, bw, zw, t visible

    // ---- Precomputed addresses ----
    const uint32_t aw = sbase + A_OFF + (uint32_t)wid * 8192u;
    const char* zw_row = smem + ZW_OFF + wid * 16384 + lane * 16;
    const uint32_t st_ch   = (uint32_t)(lane >> 1);
    const uint32_t st_half = (uint32_t)((lane & 1) << 3);
    const uint32_t a_rx   = (uint32_t)(lane & 15) & 7u;
    const uint32_t a_cs   = (uint32_t)(lane >> 4);
    const uint32_t a_rowb = (uint32_t)(lane & 15) * 256u;
    const uint32_t b_rx   = (uint32_t)(lane & 7);
    const uint32_t b_cs   = (uint32_t)((lane >> 3) & 1);
    const uint32_t b_rowb = ((uint32_t)(lane & 7) + (uint32_t)(((lane >> 4) & 1) << 3)) * 256u;
    const uint32_t bh_base = sbase + BH_OFF + b_rowb;

    const float2* sbw = (const float2*)(smem + BW_OFF);

    // ---- Hoist B fragments for n2 = 0,1 (step-invariant): 8k x 2n2 x 4 regs
    uint32_t bh_reg[8][2][4];
    #pragma unroll
    for (int k = 0; k < 8; ++k) {
        const uint32_t b_sw = ((2u * (uint32_t)k + b_cs) ^ b_rx) << 4;
        #pragma unroll
        for (int n2 = 0; n2 < 2; ++n2)
            ldsm_x4(bh_reg[k][n2], bh_base + (uint32_t)n2 * 4096u + b_sw);
    }

    #pragma unroll 1
    for (int s = 0; s < nsteps; ++s) {
        // ======= Layer 1: h1 = relu(z0 + t*wd), packed bf16x2 ==============
        #pragma unroll 4
        for (int r = 0; r < 32; ++r) {
            const float tv = t_tab[r];            // warp broadcast
            const uint32_t t2 = bf16x2_rn(tv, tv);
            const uint4 zw = *(const uint4*)(zw_row + r * 512);
            uint2 pk;
            pk.x = relu2(hfma2(t2, zw.y, zw.x));
            pk.y = relu2(hfma2(t2, zw.w, zw.z));
            const uint32_t off = (uint32_t)r * 256u
                               + ((st_ch ^ (uint32_t)(r & 7)) << 4) + st_half;
            *(uint2*)(smem + (aw - sbase) + off) = pk;
        }

        // ======= Layer 2: acc = rn(A).rn(B) ================================
        float acc[2][16][4];
        #pragma unroll
        for (int mt = 0; mt < 2; ++mt)
            #pragma unroll
            for (int nt = 0; nt < 16; ++nt)
                #pragma unroll
                for (int c = 0; c < 4; ++c) acc[mt][nt][c] = 0.f;

        #pragma unroll 2
        for (int k = 0; k < 8; ++k) {
            const uint32_t a_sw = ((2u * (uint32_t)k + a_cs) ^ a_rx) << 4;
            uint32_t ah[2][4];
            ldsm_x4(ah[0], aw + a_rowb + a_sw);
            ldsm_x4(ah[1], aw + 4096u + a_rowb + a_sw);
            const uint32_t b_sw = ((2u * (uint32_t)k + b_cs) ^ b_rx) << 4;
            // n2 = 0,1 from registers (step-invariant hoist)
            #pragma unroll
            for (int n2 = 0; n2 < 2; ++n2) {
                #pragma unroll
                for (int mt = 0; mt < 2; ++mt) {
                    mma_bf16(acc[mt][2 * n2],     ah[mt], bh_reg[k][n2][0], bh_reg[k][n2][1]);
                    mma_bf16(acc[mt][2 * n2 + 1], ah[mt], bh_reg[k][n2][2], bh_reg[k][n2][3]);
                }
            }
            // n2 = 2..7 from shared
            #pragma unroll
            for (int n2 = 2; n2 < 8; ++n2) {
                uint32_t bh[4];
                ldsm_x4(bh, bh_base + (uint32_t)n2 * 4096u + b_sw);
                #pragma unroll
                for (int mt = 0; mt < 2; ++mt) {
                    mma_bf16(acc[mt][2 * n2],     ah[mt], bh[0], bh[1]);
                    mma_bf16(acc[mt][2 * n2 + 1], ah[mt], bh[2], bh[3]);
                }
            }
        }

        // ======= Epilogue: sdf = b3 + sum relu(h2+b2)*w3; t += sdf =========
        float part[4] = {0.f, 0.f, 0.f, 0.f};
        #pragma unroll
        for (int nt = 0; nt < 16; ++nt) {
            const int n0 = nt * 8 + 2 * (lane & 3);
            const float2 bw0 = sbw[n0];
            const float2 bw1 = sbw[n0 + 1];
            #pragma unroll
            for (int mt = 0; mt < 2; ++mt) {
                const float* c = acc[mt][nt];
                part[2 * mt]     = fmaf(fmaxf(c[0] + bw0.x, 0.f), bw0.y, part[2 * mt]);
                part[2 * mt]     = fmaf(fmaxf(c[1] + bw1.x, 0.f), bw1.y, part[2 * mt]);
                part[2 * mt + 1] = fmaf(fmaxf(c[2] + bw0.x, 0.f), bw0.y, part[2 * mt + 1]);
                part[2 * mt + 1] = fmaf(fmaxf(c[3] + bw1.x, 0.f), bw1.y, part[2 * mt + 1]);
            }
        }
        #pragma unroll
        for (int c = 0; c < 4; ++c) {
            part[c] += __shfl_xor_sync(0xffffffffu, part[c], 1);
            part[c] += __shfl_xor_sync(0xffffffffu, part[c], 2);
        }
        if ((lane & 3) == 0) {
            const int q = lane >> 2;
            t_tab[q]      += part[0] + bias3;
            t_tab[q + 8]  += part[1] + bias3;
            t_tab[q + 16] += part[2] + bias3;
            t_tab[q + 24] += part[3] + bias3;
        }
        __syncwarp();
    }

    // ---- Final: p = p0 + t*d in fp32 ----
    const float t = t_tab[lane];
    out[ray * 3 + 0] = fmaf(t, dx, pos[ray * 3 + 0]);
    out[ray * 3 + 1] = fmaf(t, dy, pos[ray * 3 + 1]);
    out[ray * 3 + 2] = fmaf(t, dz, pos[ray * 3 + 2]);
}

extern "C" void kernel_launch(void* const* d_in, const int* in_sizes, int n_in,
                              void* d_out, int out_size) {
    const float* pos = (const float*)d_in[0];
    const float* dir = (const float*)d_in[1];
    const float* W1  = (const float*)d_in[2];
    const float* b1  = (const float*)d_in[3];
    const float* W2  = (const float*)d_in[4];
    const float* b2  = (const float*)d_in[5];
    const float* W3  = (const float*)d_in[6];
    const float* b3  = (const float*)d_in[7];
    const int* steps = (const int*)d_in[8];

    const int n_rays   = in_sizes[0] / 3;
    const int n_blocks = n_rays / TPB;  // 256 rays per CTA

    cudaFuncSetAttribute(sdf_march_mma,
                         cudaFuncAttributeMaxDynamicSharedMemorySize, SMEM_TOTAL);

    sdf_march_mma<<<n_blocks, TPB, SMEM_TOTAL>>>(
        pos, dir, W1, b1, W2, b2, W3, b3, steps, (float*)d_out);
}

// round 16
// speedup vs baseline: 1.1996x; 1.1996x over previous
#include <cuda_runtime.h>
#include <cuda_bf16.h>
#include <cstdint>

#define TPB   256
#define WARPS 8

// ---- smem layout (bytes) ----
// A:  per-warp h1 tile (rn bf16), 32 rows x 128 cols, 256B rows, swizzled.
// B:  rn(W2^T) 128x128 bf16, swizzled.
// ZW: per-warp z0/wd tables (layer 1 is z = z0 + t*wd; sphere tracing is
//     linear in p).  T: per-warp accumulated march distance.
// B fragments for n2 in {0,1} hoisted to registers; the k-loop is FULLY
// unrolled so bh_reg indices are compile-time constants (R15 lesson: with
// partial unroll the array is dynamically indexed -> local memory spill).
static constexpr int A_OFF   = 0;         // 8 * 8192   = 65536
static constexpr int BH_OFF  = 65536;     //              32768
static constexpr int ZW_OFF  = 98304;     // 8 * 16384  = 131072
static constexpr int BW_OFF  = 229376;    // 128 float2 = 1024
static constexpr int T_OFF   = 230400;    // 8 * 32 f32 = 1024
static constexpr int SMEM_TOTAL = 231424; // < 232448 (227KB cap)

static __device__ __forceinline__ uint32_t smem_u32(const void* p) {
    uint32_t a;
    asm("{ .reg .u64 t; cvta.to.shared.u64 t, %1; cvt.u32.u64 %0, t; }"
        : "=r"(a) : "l"(p));
    return a;
}

static __device__ __forceinline__ void ldsm_x4(uint32_t (&r)[4], uint32_t addr) {
    asm volatile("ldmatrix.sync.aligned.m8n8.x4.shared.b16 {%0,%1,%2,%3}, [%4];"
                 : "=r"(r[0]), "=r"(r[1]), "=r"(r[2]), "=r"(r[3]) : "r"(addr));
}

static __device__ __forceinline__ void mma_bf16(float* d, const uint32_t (&a)[4],
                                                uint32_t b0, uint32_t b1) {
    asm volatile(
        "mma.sync.aligned.m16n8k16.row.col.f32.bf16.bf16.f32 "
        "{%0,%1,%2,%3}, {%4,%5,%6,%7}, {%8,%9}, {%0,%1,%2,%3};"
        : "+f"(d[0]), "+f"(d[1]), "+f"(d[2]), "+f"(d[3])
        : "r"(a[0]), "r"(a[1]), "r"(a[2]), "r"(a[3]), "r"(b0), "r"(b1));
}

// bf16x2 pack of (lo, hi) with rn.
static __device__ __forceinline__ uint32_t bf16x2_rn(float lo, float hi) {
    uint32_t r;
    asm("cvt.rn.bf16x2.f32 %0, %1, %2;" : "=r"(r) : "f"(hi), "f"(lo));
    return r;
}

// Packed bf16x2 fma / relu.
static __device__ __forceinline__ uint32_t hfma2(uint32_t a, uint32_t b, uint32_t c) {
    uint32_t r;
    asm("fma.rn.bf16x2 %0, %1, %2, %3;" : "=r"(r) : "r"(a), "r"(b), "r"(c));
    return r;
}
static __device__ __forceinline__ uint32_t relu2(uint32_t a) {
    uint32_t r;
    asm("max.bf16x2 %0, %1, %2;" : "=r"(r) : "r"(a), "r"(0u));
    return r;
}

extern __shared__ char smem[];

__global__ void __launch_bounds__(TPB)
sdf_march_mma(const float* __restrict__ pos, const float* __restrict__ dir,
              const float* __restrict__ W1, const float* __restrict__ b1,
              const float* __restrict__ W2, const float* __restrict__ b2,
              const float* __restrict__ W3, const float* __restrict__ b3,
              const int* __restrict__ steps_ptr, float* __restrict__ out)
{
    const int tid  = threadIdx.x;
    const int wid  = tid >> 5;
    const int lane = tid & 31;
    const uint32_t sbase = smem_u32(smem);

    // ---- Stage B = rn(W2^T), swizzled ----
    for (int idx = tid; idx < 128 * 128; idx += TPB) {
        const int k = idx >> 7;    // reduction dim i
        const int n = idx & 127;   // output dim j
        const uint32_t off = (uint32_t)n * 256u
                           + (uint32_t)(((k >> 3) ^ (n & 7)) << 4)
                           + (uint32_t)((k & 7) << 1);
        *(__nv_bfloat16*)(smem + BH_OFF + off) = __float2bfloat16(W2[idx]);
    }
    if (tid < 128) {
        ((float2*)(smem + BW_OFF))[tid] = make_float2(b2[tid], W3[tid]);
    }

    // ---- Stage ZW: z0 = W1^T p0 + b1, wd = W1^T d for this warp's rays ----
    {
        const int i0 = lane * 4;
        float w1x[4], w1y[4], w1z[4], b1c[4];
        #pragma unroll
        for (int c = 0; c < 4; ++c) {
            w1x[c] = W1[i0 + c];
            w1y[c] = W1[128 + i0 + c];
            w1z[c] = W1[256 + i0 + c];
            b1c[c] = b1[i0 + c];
        }
        char* zw_warp = smem + ZW_OFF + wid * 16384;
        for (int r = 0; r < 32; ++r) {
            const int gr = blockIdx.x * TPB + wid * 32 + r;
            const float px = pos[gr * 3 + 0], py = pos[gr * 3 + 1], pz = pos[gr * 3 + 2];
            const float qx = dir[gr * 3 + 0], qy = dir[gr * 3 + 1], qz = dir[gr * 3 + 2];
            float z0[4], wd[4];
            #pragma unroll
            for (int c = 0; c < 4; ++c) {
                z0[c] = fmaf(px, w1x[c], fmaf(py, w1y[c], fmaf(pz, w1z[c], b1c[c])));
                wd[c] = fmaf(qx, w1x[c], fmaf(qy, w1y[c], qz * w1z[c]));
            }
            uint4 pk;
            pk.x = bf16x2_rn(z0[0], z0[1]);
            pk.y = bf16x2_rn(wd[0], wd[1]);
            pk.z = bf16x2_rn(z0[2], z0[3]);
            pk.w = bf16x2_rn(wd[2], wd[3]);
            *(uint4*)(zw_warp + r * 512 + lane * 16) = pk;
        }
    }

    // ---- Per-ray state: t = 0 ----
    const int ray = blockIdx.x * TPB + tid;
    const float dx = dir[ray * 3 + 0], dy = dir[ray * 3 + 1], dz = dir[ray * 3 + 2];
    float* t_tab = (float*)(smem + T_OFF) + wid * 32;
    t_tab[lane] = 0.f;

    const float bias3 = b3[0];
    const int nsteps = steps_ptr[0];

    __syncthreads();  // B, bw, zw, t visible

    // ---- Precomputed addresses ----
    const uint32_t aw = sbase + A_OFF + (uint32_t)wid * 8192u;
    const char* zw_row = smem + ZW_OFF + wid * 16384 + lane * 16;
    const uint32_t st_ch   = (uint32_t)(lane >> 1);
    const uint32_t st_half = (uint32_t)((lane & 1) << 3);
    const uint32_t a_rx   = (uint32_t)(lane & 15) & 7u;
    const uint32_t a_cs   = (uint32_t)(lane >> 4);
    const uint32_t a_rowb = (uint32_t)(lane & 15) * 256u;
    const uint32_t b_rx   = (uint32_t)(lane & 7);
    const uint32_t b_cs   = (uint32_t)((lane >> 3) & 1);
    const uint32_t b_rowb = ((uint32_t)(lane & 7) + (uint32_t)(((lane >> 4) & 1) << 3)) * 256u;
    const uint32_t bh_base = sbase + BH_OFF + b_rowb;

    const float2* sbw = (const float2*)(smem + BW_OFF);

    // ---- Hoist B fragments for n2 = 0,1 (step-invariant): 64 regs.
    // All consuming loops below are FULLY unrolled so indices are constant.
    uint32_t bh_reg[8][2][4];
    #pragma unroll
    for (int k = 0; k < 8; ++k) {
        const uint32_t b_sw = ((2u * (uint32_t)k + b_cs) ^ b_rx) << 4;
        #pragma unroll
        for (int n2 = 0; n2 < 2; ++n2)
            ldsm_x4(bh_reg[k][n2], bh_base + (uint32_t)n2 * 4096u + b_sw);
    }

    #pragma unroll 1
    for (int s = 0; s < nsteps; ++s) {
        // ======= Layer 1: h1 = relu(z0 + t*wd), packed bf16x2 ==============
        #pragma unroll 4
        for (int r = 0; r < 32; ++r) {
            const float tv = t_tab[r];            // warp broadcast
            const uint32_t t2 = bf16x2_rn(tv, tv);
            const uint4 zw = *(const uint4*)(zw_row + r * 512);
            uint2 pk;
            pk.x = relu2(hfma2(t2, zw.y, zw.x));
            pk.y = relu2(hfma2(t2, zw.w, zw.z));
            const uint32_t off = (uint32_t)r * 256u
                               + ((st_ch ^ (uint32_t)(r & 7)) << 4) + st_half;
            *(uint2*)(smem + (aw - sbase) + off) = pk;
        }

        // ======= Layer 2: acc = rn(A).rn(B), k fully unrolled ==============
        float acc[2][16][4];
        #pragma unroll
        for (int mt = 0; mt < 2; ++mt)
            #pragma unroll
            for (int nt = 0; nt < 16; ++nt)
                #pragma unroll
                for (int c = 0; c < 4; ++c) acc[mt][nt][c] = 0.f;

        #pragma unroll
        for (int k = 0; k < 8; ++k) {
            const uint32_t a_sw = ((2u * (uint32_t)k + a_cs) ^ a_rx) << 4;
            uint32_t ah[2][4];
            ldsm_x4(ah[0], aw + a_rowb + a_sw);
            ldsm_x4(ah[1], aw + 4096u + a_rowb + a_sw);
            const uint32_t b_sw = ((2u * (uint32_t)k + b_cs) ^ b_rx) << 4;
            // n2 = 0,1 from registers (constant indices after full unroll)
            #pragma unroll
            for (int n2 = 0; n2 < 2; ++n2) {
                #pragma unroll
                for (int mt = 0; mt < 2; ++mt) {
                    mma_bf16(acc[mt][2 * n2],     ah[mt], bh_reg[k][n2][0], bh_reg[k][n2][1]);
                    mma_bf16(acc[mt][2 * n2 + 1], ah[mt], bh_reg[k][n2][2], bh_reg[k][n2][3]);
                }
            }
            // n2 = 2..7 from shared
            #pragma unroll
            for (int n2 = 2; n2 < 8; ++n2) {
                uint32_t bh[4];
                ldsm_x4(bh, bh_base + (uint32_t)n2 * 4096u + b_sw);
                #pragma unroll
                for (int mt = 0; mt < 2; ++mt) {
                    mma_bf16(acc[mt][2 * n2],     ah[mt], bh[0], bh[1]);
                    mma_bf16(acc[mt][2 * n2 + 1], ah[mt], bh[2], bh[3]);
                }
            }
        }

        // ======= Epilogue: sdf = b3 + sum relu(h2+b2)*w3; t += sdf =========
        float part[4] = {0.f, 0.f, 0.f, 0.f};
        #pragma unroll
        for (int nt = 0; nt < 16; ++nt) {
            const int n0 = nt * 8 + 2 * (lane & 3);
            const float2 bw0 = sbw[n0];
            const float2 bw1 = sbw[n0 + 1];
            #pragma unroll
            for (int mt = 0; mt < 2; ++mt) {
                const float* c = acc[mt][nt];
                part[2 * mt]     = fmaf(fmaxf(c[0] + bw0.x, 0.f), bw0.y, part[2 * mt]);
                part[2 * mt]     = fmaf(fmaxf(c[1] + bw1.x, 0.f), bw1.y, part[2 * mt]);
                part[2 * mt + 1] = fmaf(fmaxf(c[2] + bw0.x, 0.f), bw0.y, part[2 * mt + 1]);
                part[2 * mt + 1] = fmaf(fmaxf(c[3] + bw1.x, 0.f), bw1.y, part[2 * mt + 1]);
            }
        }
        #pragma unroll
        for (int c = 0; c < 4; ++c) {
            part[c] += __shfl_xor_sync(0xffffffffu, part[c], 1);
            part[c] += __shfl_xor_sync(0xffffffffu, part[c], 2);
        }
        if ((lane & 3) == 0) {
            const int q = lane >> 2;
            t_tab[q]      += part[0] + bias3;
            t_tab[q + 8]  += part[1] + bias3;
            t_tab[q + 16] += part[2] + bias3;
            t_tab[q + 24] += part[3] + bias3;
        }
        __syncwarp();
    }

    // ---- Final: p = p0 + t*d in fp32 ----
    const float t = t_tab[lane];
    out[ray * 3 + 0] = fmaf(t, dx, pos[ray * 3 + 0]);
    out[ray * 3 + 1] = fmaf(t, dy, pos[ray * 3 + 1]);
    out[ray * 3 + 2] = fmaf(t, dz, pos[ray * 3 + 2]);
}

extern "C" void kernel_launch(void* const* d_in, const int* in_sizes, int n_in,
                              void* d_out, int out_size) {
    const float* pos = (const float*)d_in[0];
    const float* dir = (const float*)d_in[1];
    const float* W1  = (const float*)d_in[2];
    const float* b1  = (const float*)d_in[3];
    const float* W2  = (const float*)d_in[4];
    const float* b2  = (const float*)d_in[5];
    const float* W3  = (const float*)d_in[6];
    const float* b3  = (const float*)d_in[7];
    const int* steps = (const int*)d_in[8];

    const int n_rays   = in_sizes[0] / 3;
    const int n_blocks = n_rays / TPB;  // 256 rays per CTA

    cudaFuncSetAttribute(sdf_march_mma,
                         cudaFuncAttributeMaxDynamicSharedMemorySize, SMEM_TOTAL);

    sdf_march_mma<<<n_blocks, TPB, SMEM_TOTAL>>>(
        pos, dir, W1, b1, W2, b2, W3, b3, steps, (float*)d_out);
}

// round 17
// speedup vs baseline: 1.2237x; 1.0201x over previous
#include <cuda_runtime.h>
#include <cuda_bf16.h>
#include <cstdint>

#define TPB   256
#define WARPS 8

// ---- smem layout (bytes) ----
// A:  per-warp h1 tile (rn bf16), 32 rows x 128 cols, 256B rows, swizzled.
// B:  rn(W2^T) 128x128 bf16, swizzled.
// ZW: per-warp z0/wd tables (layer 1 is z = z0 + t*wd).
// SB2: b2 as fp32 (folded into acc init).  W3F: per-(kchunk, lane&3) w3
//      B-fragments for the MMA epilogue (all 8 n-cols identical -> the
//      j-reduction sdf = sum relu(h2+b2)*w3 is one m16n8k16 MMA chain and
//      needs NO shuffles).  T: per-warp accumulated march distance.
static constexpr int A_OFF   = 0;         // 8 * 8192   = 65536
static constexpr int BH_OFF  = 65536;     //              32768
static constexpr int ZW_OFF  = 98304;     // 8 * 16384  = 131072
static constexpr int SB2_OFF = 229376;    // 128 f32    = 512
static constexpr int W3F_OFF = 229888;    // 8*4 uint2  = 256
static constexpr int T_OFF   = 230400;    // 8 * 32 f32 = 1024
static constexpr int SMEM_TOTAL = 231424; // < 232448 (227KB cap)

static __device__ __forceinline__ uint32_t smem_u32(const void* p) {
    uint32_t a;
    asm("{ .reg .u64 t; cvta.to.shared.u64 t, %1; cvt.u32.u64 %0, t; }"
        : "=r"(a) : "l"(p));
    return a;
}

static __device__ __forceinline__ void ldsm_x4(uint32_t (&r)[4], uint32_t addr) {
    asm volatile("ldmatrix.sync.aligned.m8n8.x4.shared.b16 {%0,%1,%2,%3}, [%4];"
                 : "=r"(r[0]), "=r"(r[1]), "=r"(r[2]), "=r"(r[3]) : "r"(addr));
}

static __device__ __forceinline__ void mma_bf16(float* d, const uint32_t (&a)[4],
                                                uint32_t b0, uint32_t b1) {
    asm volatile(
        "mma.sync.aligned.m16n8k16.row.col.f32.bf16.bf16.f32 "
        "{%0,%1,%2,%3}, {%4,%5,%6,%7}, {%8,%9}, {%0,%1,%2,%3};"
        : "+f"(d[0]), "+f"(d[1]), "+f"(d[2]), "+f"(d[3])
        : "r"(a[0]), "r"(a[1]), "r"(a[2]), "r"(a[3]), "r"(b0), "r"(b1));
}

// bf16x2 pack of (lo, hi) with rn.
static __device__ __forceinline__ uint32_t bf16x2_rn(float lo, float hi) {
    uint32_t r;
    asm("cvt.rn.bf16x2.f32 %0, %1, %2;" : "=r"(r) : "f"(hi), "f"(lo));
    return r;
}

// Packed bf16x2 fma / relu.
static __device__ __forceinline__ uint32_t hfma2(uint32_t a, uint32_t b, uint32_t c) {
    uint32_t r;
    asm("fma.rn.bf16x2 %0, %1, %2, %3;" : "=r"(r) : "r"(a), "r"(b), "r"(c));
    return r;
}
static __device__ __forceinline__ uint32_t relu2(uint32_t a) {
    uint32_t r;
    asm("max.bf16x2 %0, %1, %2;" : "=r"(r) : "r"(a), "r"(0u));
    return r;
}

extern __shared__ char smem[];

__global__ void __launch_bounds__(TPB)
sdf_march_mma(const float* __restrict__ pos, const float* __restrict__ dir,
              const float* __restrict__ W1, const float* __restrict__ b1,
              const float* __restrict__ W2, const float* __restrict__ b2,
              const float* __restrict__ W3, const float* __restrict__ b3,
              const int* __restrict__ steps_ptr, float* __restrict__ out)
{
    const int tid  = threadIdx.x;
    const int wid  = tid >> 5;
    const int lane = tid & 31;
    const uint32_t sbase = smem_u32(smem);

    // ---- Stage B = rn(W2^T), swizzled ----
    for (int idx = tid; idx < 128 * 128; idx += TPB) {
        const int k = idx >> 7;    // reduction dim i
        const int n = idx & 127;   // output dim j
        const uint32_t off = (uint32_t)n * 256u
                           + (uint32_t)(((k >> 3) ^ (n & 7)) << 4)
                           + (uint32_t)((k & 7) << 1);
        *(__nv_bfloat16*)(smem + BH_OFF + off) = __float2bfloat16(W2[idx]);
    }
    if (tid < 128) {
        ((float*)(smem + SB2_OFF))[tid] = b2[tid];
    }
    if (tid < 32) {
        // w3 B-fragment table: entry (kc = tid>>2, l2 = tid&3).
        const int kc = tid >> 2, l2 = tid & 3;
        uint2 w;
        w.x = bf16x2_rn(W3[kc * 16 + 2 * l2],     W3[kc * 16 + 2 * l2 + 1]);
        w.y = bf16x2_rn(W3[kc * 16 + 8 + 2 * l2], W3[kc * 16 + 8 + 2 * l2 + 1]);
        ((uint2*)(smem + W3F_OFF))[tid] = w;
    }

    // ---- Stage ZW: z0 = W1^T p0 + b1, wd = W1^T d for this warp's rays ----
    {
        const int i0 = lane * 4;
        float w1x[4], w1y[4], w1z[4], b1c[4];
        #pragma unroll
        for (int c = 0; c < 4; ++c) {
            w1x[c] = W1[i0 + c];
            w1y[c] = W1[128 + i0 + c];
            w1z[c] = W1[256 + i0 + c];
            b1c[c] = b1[i0 + c];
        }
        char* zw_warp = smem + ZW_OFF + wid * 16384;
        for (int r = 0; r < 32; ++r) {
            const int gr = blockIdx.x * TPB + wid * 32 + r;
            const float px = pos[gr * 3 + 0], py = pos[gr * 3 + 1], pz = pos[gr * 3 + 2];
            const float qx = dir[gr * 3 + 0], qy = dir[gr * 3 + 1], qz = dir[gr * 3 + 2];
            float z0[4], wd[4];
            #pragma unroll
            for (int c = 0; c < 4; ++c) {
                z0[c] = fmaf(px, w1x[c], fmaf(py, w1y[c], fmaf(pz, w1z[c], b1c[c])));
                wd[c] = fmaf(qx, w1x[c], fmaf(qy, w1y[c], qz * w1z[c]));
            }
            uint4 pk;
            pk.x = bf16x2_rn(z0[0], z0[1]);
            pk.y = bf16x2_rn(wd[0], wd[1]);
            pk.z = bf16x2_rn(z0[2], z0[3]);
            pk.w = bf16x2_rn(wd[2], wd[3]);
            *(uint4*)(zw_warp + r * 512 + lane * 16) = pk;
        }
    }

    // ---- Per-ray state: t = 0 ----
    const int ray = blockIdx.x * TPB + tid;
    const float dx = dir[ray * 3 + 0], dy = dir[ray * 3 + 1], dz = dir[ray * 3 + 2];
    float* t_tab = (float*)(smem + T_OFF) + wid * 32;
    t_tab[lane] = 0.f;

    const float bias3 = b3[0];
    const int nsteps = steps_ptr[0];

    __syncthreads();  // B, sb2, w3f, zw, t visible

    // ---- Precomputed addresses ----
    const uint32_t aw = sbase + A_OFF + (uint32_t)wid * 8192u;
    const char* zw_row = smem + ZW_OFF + wid * 16384 + lane * 16;
    const uint32_t st_ch   = (uint32_t)(lane >> 1);
    const uint32_t st_half = (uint32_t)((lane & 1) << 3);
    const uint32_t a_rx   = (uint32_t)(lane & 15) & 7u;
    const uint32_t a_cs   = (uint32_t)(lane >> 4);
    const uint32_t a_rowb = (uint32_t)(lane & 15) * 256u;
    const uint32_t b_rx   = (uint32_t)(lane & 7);
    const uint32_t b_cs   = (uint32_t)((lane >> 3) & 1);
    const uint32_t b_rowb = ((uint32_t)(lane & 7) + (uint32_t)(((lane >> 4) & 1) << 3)) * 256u;
    const uint32_t bh_base = sbase + BH_OFF + b_rowb;

    const float* sb2 = (const float*)(smem + SB2_OFF);
    const uint2* w3f = (const uint2*)(smem + W3F_OFF);

    // ---- Hoist B fragments for n2 = 0,1 (step-invariant): 64 regs. ----
    uint32_t bh_reg[8][2][4];
    #pragma unroll
    for (int k = 0; k < 8; ++k) {
        const uint32_t b_sw = ((2u * (uint32_t)k + b_cs) ^ b_rx) << 4;
        #pragma unroll
        for (int n2 = 0; n2 < 2; ++n2)
            ldsm_x4(bh_reg[k][n2], bh_base + (uint32_t)n2 * 4096u + b_sw);
    }

    #pragma unroll 1
    for (int s = 0; s < nsteps; ++s) {
        // ======= Layer 1: h1 = relu(z0 + t*wd), packed bf16x2 ==============
        #pragma unroll 4
        for (int r = 0; r < 32; ++r) {
            const float tv = t_tab[r];            // warp broadcast
            const uint32_t t2 = bf16x2_rn(tv, tv);
            const uint4 zw = *(const uint4*)(zw_row + r * 512);
            uint2 pk;
            pk.x = relu2(hfma2(t2, zw.y, zw.x));
            pk.y = relu2(hfma2(t2, zw.w, zw.z));
            const uint32_t off = (uint32_t)r * 256u
                               + ((st_ch ^ (uint32_t)(r & 7)) << 4) + st_half;
            *(uint2*)(smem + (aw - sbase) + off) = pk;
        }

        // ======= Layer 2: acc = b2 + rn(A).rn(B), k fully unrolled =========
        float acc[2][16][4];
        #pragma unroll
        for (int nt = 0; nt < 16; ++nt) {
            const float2 b2v = *(const float2*)(sb2 + nt * 8 + 2 * (lane & 3));
            #pragma unroll
            for (int mt = 0; mt < 2; ++mt) {
                acc[mt][nt][0] = b2v.x;
                acc[mt][nt][1] = b2v.y;
                acc[mt][nt][2] = b2v.x;
                acc[mt][nt][3] = b2v.y;
            }
        }

        #pragma unroll
        for (int k = 0; k < 8; ++k) {
            const uint32_t a_sw = ((2u * (uint32_t)k + a_cs) ^ a_rx) << 4;
            uint32_t ah[2][4];
            ldsm_x4(ah[0], aw + a_rowb + a_sw);
            ldsm_x4(ah[1], aw + 4096u + a_rowb + a_sw);
            const uint32_t b_sw = ((2u * (uint32_t)k + b_cs) ^ b_rx) << 4;
            #pragma unroll
            for (int n2 = 0; n2 < 2; ++n2) {
                #pragma unroll
                for (int mt = 0; mt < 2; ++mt) {
                    mma_bf16(acc[mt][2 * n2],     ah[mt], bh_reg[k][n2][0], bh_reg[k][n2][1]);
                    mma_bf16(acc[mt][2 * n2 + 1], ah[mt], bh_reg[k][n2][2], bh_reg[k][n2][3]);
                }
            }
            #pragma unroll
            for (int n2 = 2; n2 < 8; ++n2) {
                uint32_t bh[4];
                ldsm_x4(bh, bh_base + (uint32_t)n2 * 4096u + b_sw);
                #pragma unroll
                for (int mt = 0; mt < 2; ++mt) {
                    mma_bf16(acc[mt][2 * n2],     ah[mt], bh[0], bh[1]);
                    mma_bf16(acc[mt][2 * n2 + 1], ah[mt], bh[2], bh[3]);
                }
            }
        }

        // ======= Epilogue as MMA: sdf = relu(acc) . w3 =====================
        // acc pairs (2kc, 2kc+1) are exactly A-fragment layout for k16 chunk
        // kc; B' = w3 fragments (all 8 n-cols identical) -> acc2 columns all
        // equal the full j-dot.  No shuffles.
        float acc2[2][4];
        #pragma unroll
        for (int mt = 0; mt < 2; ++mt)
            #pragma unroll
            for (int c = 0; c < 4; ++c) acc2[mt][c] = 0.f;

        #pragma unroll
        for (int kc = 0; kc < 8; ++kc) {
            const uint2 w3v = w3f[kc * 4 + (lane & 3)];
            #pragma unroll
            for (int mt = 0; mt < 2; ++mt) {
                uint32_t af[4];
                af[0] = relu2(bf16x2_rn(acc[mt][2 * kc][0],     acc[mt][2 * kc][1]));
                af[1] = relu2(bf16x2_rn(acc[mt][2 * kc][2],     acc[mt][2 * kc][3]));
                af[2] = relu2(bf16x2_rn(acc[mt][2 * kc + 1][0], acc[mt][2 * kc + 1][1]));
                af[3] = relu2(bf16x2_rn(acc[mt][2 * kc + 1][2], acc[mt][2 * kc + 1][3]));
                mma_bf16(acc2[mt], af, w3v.x, w3v.y);
            }
        }

        if ((lane & 3) == 0) {
            const int q = lane >> 2;
            t_tab[q]      += acc2[0][0] + bias3;   // ray q      (mt0, row q)
            t_tab[q + 8]  += acc2[0][2] + bias3;   // ray q+8
            t_tab[q + 16] += acc2[1][0] + bias3;   // ray q+16   (mt1)
            t_tab[q + 24] += acc2[1][2] + bias3;   // ray q+24
        }
        __syncwarp();
    }

    // ---- Final: p = p0 + t*d in fp32 ----
    const float t = t_tab[lane];
    out[ray * 3 + 0] = fmaf(t, dx, pos[ray * 3 + 0]);
    out[ray * 3 + 1] = fmaf(t, dy, pos[ray * 3 + 1]);
    out[ray * 3 + 2] = fmaf(t, dz, pos[ray * 3 + 2]);
}

extern "C" void kernel_launch(void* const* d_in, const int* in_sizes, int n_in,
                              void* d_out, int out_size) {
    const float* pos = (const float*)d_in[0];
    const float* dir = (const float*)d_in[1];
    const float* W1  = (const float*)d_in[2];
    const float* b1  = (const float*)d_in[3];
    const float* W2  = (const float*)d_in[4];
    const float* b2  = (const float*)d_in[5];
    const float* W3  = (const float*)d_in[6];
    const float* b3  = (const float*)d_in[7];
    const int* steps = (const int*)d_in[8];

    const int n_rays   = in_sizes[0] / 3;
    const int n_blocks = n_rays / TPB;  // 256 rays per CTA

    cudaFuncSetAttribute(sdf_march_mma,
                         cudaFuncAttributeMaxDynamicSharedMemorySize, SMEM_TOTAL);

    sdf_march_mma<<<n_blocks, TPB, SMEM_TOTAL>>>(
        pos, dir, W1, b1, W2, b2, W3, b3, steps, (float*)d_out);
}